// round 11
// baseline (speedup 1.0000x reference)
#include <cuda_runtime.h>
#include <math.h>

// B=8192 rows, N=2048 anchors/row.
// Layout: 256-thread CTAs, 8 warps; each warp owns HALF a row (1024 elems).
// 4 rows/CTA -> grid 2048 -> 8 CTAs/SM -> 64 resident warps (vs 55 in R9).
// Same pf-1 pipelined 3-stream loop as R9, 8 stages per warp.
// Inputs: anchors (B,N,2) f32, offsets (B,N,2) f32, confidences (B,N) f32,
//         ground_truth (B,2) f32.  Output: 3 f32 (total, ce, huber).

#define B_SZ 8192
#define N_SZ 2048
#define NT   256
#define NW   (NT / 32)               // 8 warps
#define ROWS_PER_CTA 4
#define GRID (B_SZ / ROWS_PER_CTA)   // 2048
#define DELTA 0.04f
#define LOG_CLAMP -100.0f

__device__ __align__(16) float g_ce[B_SZ];
__device__ __align__(16) float g_hu[B_SZ];
__device__ unsigned g_count = 0;

__device__ __forceinline__ float warp_sum(float v) {
#pragma unroll
    for (int o = 16; o; o >>= 1) v += __shfl_xor_sync(0xffffffffu, v, o);
    return v;
}
__device__ __forceinline__ unsigned long long warp_min64(unsigned long long k) {
#pragma unroll
    for (int o = 16; o; o >>= 1) {
        unsigned long long ok = __shfl_xor_sync(0xffffffffu, k, o);
        k = min(k, ok);
    }
    return k;
}
__device__ __forceinline__ float huber1(float x) {
    float ax = fabsf(x);
    return (ax <= DELTA) ? 0.5f * x * x : DELTA * (ax - 0.5f * DELTA);
}

// argmin key: (float_bits(d) << 32) | idx — nonneg float bit order == value
// order, min() gives exact first-index tie-break.
__device__ __forceinline__ unsigned long long
amin2(const float4& a, int vi, float gx, float gy) {
    float dx0 = a.x - gx, dy0 = a.y - gy;
    float dx1 = a.z - gx, dy1 = a.w - gy;
    float d0 = fmaf(dx0, dx0, dy0 * dy0);
    float d1 = fmaf(dx1, dx1, dy1 * dy1);
    unsigned long long k0 = ((unsigned long long)__float_as_uint(d0) << 32) | (unsigned)(2 * vi);
    unsigned long long k1 = ((unsigned long long)__float_as_uint(d1) << 32) | (unsigned)(2 * vi + 1);
    return min(k0, k1);
}

__global__ __launch_bounds__(NT, 8) void fused_kernel(
    const float* __restrict__ anchors,
    const float* __restrict__ offsets,
    const float* __restrict__ conf,
    const float* __restrict__ gt,
    float* __restrict__ out)
{
    const int t    = threadIdx.x;
    const int warp = t >> 5, lane = t & 31;
    const int row_in_cta = warp >> 1;          // 0..3
    const int half       = warp & 1;           // 0..1
    const int b    = blockIdx.x * ROWS_PER_CTA + row_in_cta;

    __shared__ float s1s[NW], s2s[NW];
    __shared__ unsigned long long sks[NW];
    __shared__ unsigned s_arrival;

    const float gx = __ldg(&gt[2 * b]);
    const float gy = __ldg(&gt[2 * b + 1]);

    // this warp covers columns [half*1024, half*1024+1024)
    const float4* c4 = reinterpret_cast<const float4*>(conf)
                       + (size_t)b * (N_SZ / 4) + half * 256 + lane;
    const float4* a4 = reinterpret_cast<const float4*>(anchors)
                       + (size_t)b * (N_SZ / 2) + half * 512 + lane;
    const int vbase = half * 512;              // global float4 index base

    float s1a = 0.f, s1b = 0.f, s2a = 0.f, s2b = 0.f;
    unsigned long long bk = 0xFFFFFFFFFFFFFFFFull;

    // pf-1 pipeline: 8 stages of (1 conf4 + 2 anchor4); next stage's loads
    // are in flight during current compute.
    float4 cf = __ldg(c4);
    float4 a0 = __ldg(a4);
    float4 a1 = __ldg(a4 + 32);

#pragma unroll
    for (int j = 0; j < 8; j++) {
        float4 cfn, a0n, a1n;
        if (j < 7) {
            cfn = __ldg(c4 + 32 * (j + 1));
            a0n = __ldg(a4 + 64 * (j + 1));
            a1n = __ldg(a4 + 64 * (j + 1) + 32);
        }

        // softmax power sums: S1 = sum e, S2 = sum e^2
        float e0 = __expf(cf.x), e1 = __expf(cf.y);
        float e2 = __expf(cf.z), e3 = __expf(cf.w);
        s1a += e0 + e1;
        s1b += e2 + e3;
        s2a = fmaf(e0, e0, fmaf(e1, e1, s2a));
        s2b = fmaf(e2, e2, fmaf(e3, e3, s2b));

        // argmin of squared distance (sqrt monotone -> same argmin)
        bk = min(bk, amin2(a0, vbase + 64 * j + lane,      gx, gy));
        bk = min(bk, amin2(a1, vbase + 64 * j + 32 + lane, gx, gy));

        cf = cfn; a0 = a0n; a1 = a1n;
    }

    // ---- warp reduction, then combine the two half-row warps via smem ----
    float S1h = warp_sum(s1a + s1b);
    float S2h = warp_sum(s2a + s2b);
    bk = warp_min64(bk);
    if (lane == 0) { s1s[warp] = S1h; s2s[warp] = S2h; sks[warp] = bk; }
    __syncthreads();

    if (half == 0 && lane == 0) {
        const float S1 = s1s[warp] + s1s[warp + 1];
        const float S2 = s2s[warp] + s2s[warp + 1];
        const unsigned long long bkr = min(sks[warp], sks[warp + 1]);
        const int biall = (int)(bkr & 0xFFFFFFFFull);

        // sum_n log1p(-p_n) ~= -(1 + S2/(2 S1^2)); higher terms < 2e-6/row
        const float inv = 1.0f / S1;
        float polySum = -fmaf(0.5f * S2 * inv, inv, 1.0f);

        // exact terms at the argmin index
        float c_idx = __ldg(&conf[(size_t)b * N_SZ + biall]);
        float e_idx = __expf(c_idx);
        float u_idx = e_idx * inv;
        float lp    = fmaxf(__logf(u_idx), LOG_CLAMP);
        float l1    = fmaxf(log1pf(-u_idx), LOG_CLAMP);
        float ce    = -(lp + polySum - l1);

        // Huber on gathered closest anchor/offset
        const float* ap = anchors + (size_t)b * N_SZ * 2 + 2 * biall;
        const float* op = offsets + (size_t)b * N_SZ * 2 + 2 * biall;
        float ax = __ldg(&ap[0]), ay = __ldg(&ap[1]);
        float ox = __ldg(&op[0]), oy = __ldg(&op[1]);
        float hu = huber1(ox - (gx - ax)) + huber1(oy - (gy - ay));

        g_ce[b] = ce;
        g_hu[b] = hu;
        __threadfence();          // publish before this CTA signals arrival
    }

    __syncthreads();
    if (t == 0) {
        __threadfence();
        s_arrival = atomicAdd(&g_count, 1u);
    }
    __syncthreads();

    // ---- last CTA: deterministic fixed-order 8192 -> 3 reduction ----
    if (s_arrival == GRID - 1) {
        __threadfence();
        float ce = 0.f, hu = 0.f;
        const float4* ce4 = reinterpret_cast<const float4*>(g_ce);
        const float4* hu4 = reinterpret_cast<const float4*>(g_hu);
#pragma unroll
        for (int k = 0; k < 8; k++) {     // thread t owns [t*32, t*32+32)
            float4 v = ce4[t * 8 + k];
            ce += (v.x + v.y) + (v.z + v.w);
        }
#pragma unroll
        for (int k = 0; k < 8; k++) {
            float4 v = hu4[t * 8 + k];
            hu += (v.x + v.y) + (v.z + v.w);
        }
        ce = warp_sum(ce);
        hu = warp_sum(hu);
        if (lane == 0) { s1s[warp] = ce; s2s[warp] = hu; }
        __syncthreads();
        if (t == 0) {
            float cet = s1s[0], hut = s2s[0];
#pragma unroll
            for (int w = 1; w < NW; w++) { cet += s1s[w]; hut += s2s[w]; }
            out[0] = cet + hut;
            out[1] = cet;
            out[2] = hut;
            g_count = 0;          // reset for next graph replay
        }
    }
}

extern "C" void kernel_launch(void* const* d_in, const int* in_sizes, int n_in,
                              void* d_out, int out_size)
{
    const float* anchors = (const float*)d_in[0];
    const float* offsets = (const float*)d_in[1];
    const float* conf    = (const float*)d_in[2];
    const float* gt      = (const float*)d_in[3];
    float* out = (float*)d_out;

    fused_kernel<<<GRID, NT>>>(anchors, offsets, conf, gt, out);
}

// round 12
// speedup vs baseline: 1.0452x; 1.0452x over previous
#include <cuda_runtime.h>
#include <math.h>

// B=8192 rows, N=2048 anchors/row. R9 base: warp-per-row, 256-thread CTAs,
// grid 1024 (single balanced wave), pf-1 software pipeline.
// R12 deltas: reg cap 36 (launch_bounds 256,7) so pf-1 fully materializes;
// __ldcs streaming loads (zero reuse -> evict-first).
// Inputs: anchors (B,N,2) f32, offsets (B,N,2) f32, confidences (B,N) f32,
//         ground_truth (B,2) f32.  Output: 3 f32 (total, ce, huber).

#define B_SZ 8192
#define N_SZ 2048
#define NT   256
#define NW   (NT / 32)
#define ROWS_PER_CTA NW
#define GRID (B_SZ / ROWS_PER_CTA)
#define DELTA 0.04f
#define LOG_CLAMP -100.0f

__device__ __align__(16) float g_ce[B_SZ];
__device__ __align__(16) float g_hu[B_SZ];
__device__ unsigned g_count = 0;

__device__ __forceinline__ float warp_sum(float v) {
#pragma unroll
    for (int o = 16; o; o >>= 1) v += __shfl_xor_sync(0xffffffffu, v, o);
    return v;
}
__device__ __forceinline__ float huber1(float x) {
    float ax = fabsf(x);
    return (ax <= DELTA) ? 0.5f * x * x : DELTA * (ax - 0.5f * DELTA);
}

// argmin key: (float_bits(d) << 32) | idx — nonneg float bit order == value
// order, min() gives exact first-index tie-break.
__device__ __forceinline__ unsigned long long
amin2(const float4& a, int vi, float gx, float gy) {
    float dx0 = a.x - gx, dy0 = a.y - gy;
    float dx1 = a.z - gx, dy1 = a.w - gy;
    float d0 = fmaf(dx0, dx0, dy0 * dy0);
    float d1 = fmaf(dx1, dx1, dy1 * dy1);
    unsigned long long k0 = ((unsigned long long)__float_as_uint(d0) << 32) | (unsigned)(2 * vi);
    unsigned long long k1 = ((unsigned long long)__float_as_uint(d1) << 32) | (unsigned)(2 * vi + 1);
    return min(k0, k1);
}

__global__ __launch_bounds__(NT, 7) void fused_kernel(
    const float* __restrict__ anchors,
    const float* __restrict__ offsets,
    const float* __restrict__ conf,
    const float* __restrict__ gt,
    float* __restrict__ out)
{
    const int t    = threadIdx.x;
    const int warp = t >> 5, lane = t & 31;
    const int b    = blockIdx.x * ROWS_PER_CTA + warp;   // this warp's row

    __shared__ float s1[NW], s2[NW];
    __shared__ unsigned s_arrival;

    const float gx = __ldg(&gt[2 * b]);
    const float gy = __ldg(&gt[2 * b + 1]);

    const float4* c4 = reinterpret_cast<const float4*>(conf)    + (size_t)b * (N_SZ / 4) + lane;
    const float4* a4 = reinterpret_cast<const float4*>(anchors) + (size_t)b * (N_SZ / 2) + lane;

    float s1a = 0.f, s1b = 0.f, s2a = 0.f, s2b = 0.f;
    unsigned long long bk = 0xFFFFFFFFFFFFFFFFull;

    // ---- software-pipelined main loop: 16 stages of (1 conf4 + 2 anchor4).
    // Stage j+1's loads issue BEFORE stage j's compute; streaming (.cs)
    // since no element is ever reused.
    float4 cf = __ldcs(c4);
    float4 a0 = __ldcs(a4);
    float4 a1 = __ldcs(a4 + 32);

#pragma unroll
    for (int j = 0; j < 16; j++) {
        float4 cfn, a0n, a1n;
        if (j < 15) {
            cfn = __ldcs(c4 + 32 * (j + 1));
            a0n = __ldcs(a4 + 64 * (j + 1));
            a1n = __ldcs(a4 + 64 * (j + 1) + 32);
        }

        // softmax power sums: S1 = sum e, S2 = sum e^2
        float e0 = __expf(cf.x), e1 = __expf(cf.y);
        float e2 = __expf(cf.z), e3 = __expf(cf.w);
        s1a += e0 + e1;
        s1b += e2 + e3;
        s2a = fmaf(e0, e0, fmaf(e1, e1, s2a));
        s2b = fmaf(e2, e2, fmaf(e3, e3, s2b));

        // argmin of squared distance (sqrt monotone -> same argmin)
        bk = min(bk, amin2(a0, 64 * j + lane,      gx, gy));
        bk = min(bk, amin2(a1, 64 * j + 32 + lane, gx, gy));

        cf = cfn; a0 = a0n; a1 = a1n;
    }

    // ---- warp-only reduction (no block barrier in hot path) ----
    float S1 = warp_sum(s1a + s1b);
    float S2 = warp_sum(s2a + s2b);
#pragma unroll
    for (int o = 16; o; o >>= 1) {
        unsigned long long ok = __shfl_xor_sync(0xffffffffu, bk, o);
        bk = min(bk, ok);
    }

    if (lane == 0) {
        const int biall = (int)(bk & 0xFFFFFFFFull);

        // sum_n log1p(-p_n) ~= -(1 + S2/(2 S1^2));  higher terms < 2e-6/row
        const float inv = 1.0f / S1;
        float polySum = -fmaf(0.5f * S2 * inv, inv, 1.0f);

        // exact terms at the argmin index
        float c_idx = __ldg(&conf[(size_t)b * N_SZ + biall]);
        float e_idx = __expf(c_idx);
        float u_idx = e_idx * inv;
        float lp    = fmaxf(__logf(u_idx), LOG_CLAMP);
        float l1    = fmaxf(log1pf(-u_idx), LOG_CLAMP);
        float ce    = -(lp + polySum - l1);

        // Huber on gathered closest anchor/offset
        const float* ap = anchors + (size_t)b * N_SZ * 2 + 2 * biall;
        const float* op = offsets + (size_t)b * N_SZ * 2 + 2 * biall;
        float ax = __ldg(&ap[0]), ay = __ldg(&ap[1]);
        float ox = __ldg(&op[0]), oy = __ldg(&op[1]);
        float hu = huber1(ox - (gx - ax)) + huber1(oy - (gy - ay));

        g_ce[b] = ce;
        g_hu[b] = hu;
        __threadfence();          // publish before this CTA signals arrival
    }

    __syncthreads();
    if (t == 0) {
        __threadfence();
        s_arrival = atomicAdd(&g_count, 1u);
    }
    __syncthreads();

    // ---- last CTA: deterministic fixed-order 8192 -> 3 reduction ----
    if (s_arrival == GRID - 1) {
        __threadfence();
        float ce = 0.f, hu = 0.f;
        const float4* ce4 = reinterpret_cast<const float4*>(g_ce);
        const float4* hu4 = reinterpret_cast<const float4*>(g_hu);
#pragma unroll
        for (int k = 0; k < 8; k++) {     // thread t owns [t*32, t*32+32)
            float4 v = ce4[t * 8 + k];
            ce += (v.x + v.y) + (v.z + v.w);
        }
#pragma unroll
        for (int k = 0; k < 8; k++) {
            float4 v = hu4[t * 8 + k];
            hu += (v.x + v.y) + (v.z + v.w);
        }
        ce = warp_sum(ce);
        hu = warp_sum(hu);
        if (lane == 0) { s1[warp] = ce; s2[warp] = hu; }
        __syncthreads();
        if (t == 0) {
            float cet = s1[0], hut = s2[0];
#pragma unroll
            for (int w = 1; w < NW; w++) { cet += s1[w]; hut += s2[w]; }
            out[0] = cet + hut;
            out[1] = cet;
            out[2] = hut;
            g_count = 0;          // reset for next graph replay
        }
    }
}

extern "C" void kernel_launch(void* const* d_in, const int* in_sizes, int n_in,
                              void* d_out, int out_size)
{
    const float* anchors = (const float*)d_in[0];
    const float* offsets = (const float*)d_in[1];
    const float* conf    = (const float*)d_in[2];
    const float* gt      = (const float*)d_in[3];
    float* out = (float*)d_out;

    fused_kernel<<<GRID, NT>>>(anchors, offsets, conf, gt, out);
}